// round 1
// baseline (speedup 1.0000x reference)
#include <cuda_runtime.h>
#include <cuda_bf16.h>
#include <cstdint>

// Problem shapes (fixed by the dataset's setup_inputs)
constexpr int B = 16;
constexpr int S = 512;
constexpr int D = 768;     // span_dim
constexpr int E = 128;     // distance embedding dim
constexpr int T = 64;
constexpr int O = 64;
constexpr int P = T * O;            // 4096 pairs per batch
constexpr int OUT_D = 2 * D + E;    // 1664 floats per output row
constexpr int D4 = D / 4;           // 192 float4
constexpr int E4 = E / 4;           // 32 float4
constexpr int OUT_D4 = OUT_D / 4;   // 416 float4

// BUCKET_BINS (14 entries). bucket = (# bins <= width) - 1; bins[0]=0 and width>=0,
// so bucket = sum_{i=1..13} (width >= bins[i]).
__constant__ int c_bins[14] = {0, 1, 2, 3, 4, 5, 7, 8, 15, 16, 31, 32, 63, 64};

__global__ __launch_bounds__(192, 8)
void pair_rep_kernel(const float4* __restrict__ spans,      // [B,S,D/4]
                     const float4* __restrict__ dist_emb,   // [14,E/4]
                     const int2*   __restrict__ span_idx,   // [S]
                     const int*    __restrict__ tgt,        // [B,T]
                     const int*    __restrict__ opi,        // [B,O]
                     float4*       __restrict__ out)        // [B*P, OUT_D/4]
{
    const int row = blockIdx.x;        // 0 .. B*P-1
    const int b = row >> 12;           // / 4096
    const int p = row & (P - 1);
    const int t = p >> 6;              // / 64
    const int o = p & (O - 1);

    const int ti = __ldg(&tgt[b * T + t]);
    const int oi = __ldg(&opi[b * O + o]);

    const int2 ab = __ldg(&span_idx[ti]);
    const int2 cd = __ldg(&span_idx[oi]);
    const int w = min(abs(ab.y - cd.x), abs(ab.x - cd.y));

    int bucket = 0;
#pragma unroll
    for (int i = 1; i < 14; ++i)
        bucket += (w >= c_bins[i]) ? 1 : 0;

    const float4* st = spans + (size_t)(b * S + ti) * D4;
    const float4* so = spans + (size_t)(b * S + oi) * D4;
    const float4* de = dist_emb + (size_t)bucket * E4;
    float4* dst = out + (size_t)row * OUT_D4;

    const int tid = threadIdx.x;       // blockDim.x == 192 == D4

    // span_t section: 192 float4, one per thread
    {
        float4 v = __ldg(&st[tid]);
        __stcs(&dst[tid], v);
    }
    // span_o section
    {
        float4 v = __ldg(&so[tid]);
        __stcs(&dst[D4 + tid], v);
    }
    // distance embedding section: first 32 threads
    if (tid < E4) {
        float4 v = __ldg(&de[tid]);
        __stcs(&dst[2 * D4 + tid], v);
    }
}

extern "C" void kernel_launch(void* const* d_in, const int* in_sizes, int n_in,
                              void* d_out, int out_size)
{
    // metadata order: spans, dist_emb, span_indices, target_indices, opinion_indices
    const float4* spans    = (const float4*)d_in[0];
    const float4* dist_emb = (const float4*)d_in[1];
    const int2*   span_idx = (const int2*)  d_in[2];
    const int*    tgt      = (const int*)   d_in[3];
    const int*    opi      = (const int*)   d_in[4];
    float4*       out      = (float4*)d_out;

    dim3 grid(B * P);   // 65536 blocks
    dim3 block(192);
    pair_rep_kernel<<<grid, block>>>(spans, dist_emb, span_idx, tgt, opi, out);
}